// round 2
// baseline (speedup 1.0000x reference)
#include <cuda_runtime.h>

#define NB    2048
#define KD    256
#define PD    256
#define SD    10
#define LAMB  0.5f
#define EPSF  1e-9f

__device__ float g_logmse[NB];
__device__ float g_pen[NB];

__device__ __forceinline__ float warp_max(float v) {
#pragma unroll
    for (int off = 16; off; off >>= 1)
        v = fmaxf(v, __shfl_xor_sync(0xffffffffu, v, off));
    return v;
}

__global__ __launch_bounds__(256, 4)
void vil_main_kernel(const float* __restrict__ y_pred,
                     const float* __restrict__ y_true,
                     const float* __restrict__ Pmat,
                     const float* __restrict__ params,
                     const float* __restrict__ Xs)
{
    __shared__ float xs[SD * KD];      // masked X tile        (10 KB)
    __shared__ float cp[SD * PD];      // |X@P| masked         (10 KB)
    __shared__ float wtop[8 * 9];      // per-warp top-9

    const int b    = blockIdx.x;
    const int tid  = threadIdx.x;
    const int lane = tid & 31;
    const int warp = tid >> 5;

    int n = (int)params[b * 3 + 0];
    int k = (int)params[b * 3 + 1];
    int m = (int)params[b * 3 + 2];
    if (k > KD) k = KD;
    int pv = n - k;
    if (pv < 0) pv = 0;
    if (pv > PD) pv = PD;
    int r = m + 1;
    if (r > 9) r = 9;

    // ---- stage masked X into smem ----
    const float* Xb = Xs + (size_t)b * SD * KD;
    for (int i = tid; i < SD * KD; i += 256) {
        int col = i & (KD - 1);
        float v = Xb[i];
        xs[i] = (col < k) ? v : 0.0f;
    }
    __syncthreads();

    // ---- GEMM: acc[s] = sum_kk xs[s][kk] * P[b][kk][tid] ----
    const float* Pb = Pmat + (size_t)b * KD * PD + tid;
    float acc[SD];
#pragma unroll
    for (int s = 0; s < SD; ++s) acc[s] = 0.0f;

    for (int kk = 0; kk < KD; kk += 8) {
        float p0 = Pb[(kk + 0) * PD];
        float p1 = Pb[(kk + 1) * PD];
        float p2 = Pb[(kk + 2) * PD];
        float p3 = Pb[(kk + 3) * PD];
        float p4 = Pb[(kk + 4) * PD];
        float p5 = Pb[(kk + 5) * PD];
        float p6 = Pb[(kk + 6) * PD];
        float p7 = Pb[(kk + 7) * PD];
#pragma unroll
        for (int s = 0; s < SD; ++s) {
            const float4* xr = reinterpret_cast<const float4*>(&xs[s * KD + kk]);
            float4 xa = xr[0];
            float4 xb = xr[1];
            float a = acc[s];
            a = fmaf(xa.x, p0, a);
            a = fmaf(xa.y, p1, a);
            a = fmaf(xa.z, p2, a);
            a = fmaf(xa.w, p3, a);
            a = fmaf(xb.x, p4, a);
            a = fmaf(xb.y, p5, a);
            a = fmaf(xb.z, p6, a);
            a = fmaf(xb.w, p7, a);
            acc[s] = a;
        }
    }

    // ---- write masked |C_p| to smem ----
#pragma unroll
    for (int s = 0; s < SD; ++s)
        cp[s * PD + tid] = (tid < pv) ? fabsf(acc[s]) : -1.0f;
    __syncthreads();

    // ---- selection: top-1 and rank-m over 512 candidates per s ----
    // merge-slot predicates (fixed per thread across s)
    const int g0 = lane, g1 = lane + 32, g2 = lane + 64;
    const bool ok0 = (g0 < 72) && ((g0 % 9) < r);
    const bool ok1 = (g1 < 72) && ((g1 % 9) < r);
    const bool ok2 = (g2 < 72) && ((g2 % 9) < r);

    float maxhm = 0.0f;   // meaningful on warp 0 only

    const int i0 = warp * 64 + lane;
    const int i1 = i0 + 32;

    for (int s = 0; s < SD; ++s) {
        // candidates for this warp's 64-element chunk
        float v0, v1;
        if (i0 < KD) v0 = (i0 < k) ? fabsf(xs[s * KD + i0]) : -1.0f;
        else         v0 = cp[s * PD + (i0 - KD)];
        if (i1 < KD) v1 = (i1 < k) ? fabsf(xs[s * KD + i1]) : -1.0f;
        else         v1 = cp[s * PD + (i1 - KD)];

        // warp-local top-r with removal
        for (int it = 0; it < r; ++it) {
            float vm = warp_max(fmaxf(v0, v1));
            if (lane == 0) wtop[warp * 9 + it] = vm;
            unsigned b0 = __ballot_sync(0xffffffffu, v0 == vm);
            if (b0) {
                if (lane == (__ffs(b0) - 1)) v0 = -3.0f;
            } else {
                unsigned b1 = __ballot_sync(0xffffffffu, v1 == vm);
                if (lane == (__ffs(b1) - 1)) v1 = -3.0f;
            }
        }
        __syncthreads();

        // warp 0 merges 8 * r candidates
        if (warp == 0) {
            float u0 = ok0 ? wtop[g0] : -3.0f;
            float u1 = ok1 ? wtop[g1] : -3.0f;
            float u2 = ok2 ? wtop[g2] : -3.0f;
            float top0 = -3.0f, topm = -3.0f;
            for (int it = 0; it < r; ++it) {
                float vm = warp_max(fmaxf(u0, fmaxf(u1, u2)));
                if (it == 0) top0 = vm;
                topm = vm;
                unsigned c0 = __ballot_sync(0xffffffffu, u0 == vm);
                if (c0) {
                    if (lane == (__ffs(c0) - 1)) u0 = -3.0f;
                } else {
                    unsigned c1 = __ballot_sync(0xffffffffu, u1 == vm);
                    if (c1) {
                        if (lane == (__ffs(c1) - 1)) u1 = -3.0f;
                    } else {
                        unsigned c2 = __ballot_sync(0xffffffffu, u2 == vm);
                        if (lane == (__ffs(c2) - 1)) u2 = -3.0f;
                    }
                }
            }
            float hm = top0 / (topm + EPSF);
            maxhm = fmaxf(maxhm, hm);
        }
        __syncthreads();
    }

    // ---- per-batch scalar outputs ----
    if (tid == 0) {
        float yp = y_pred[b];
        float lt = log2f(fmaxf(y_true[b], EPSF));
        float lp = log2f(fmaxf(yp, EPSF));
        float d  = lt - lp;
        g_logmse[b] = d * d;
        bool valid  = (m + 1) <= n;
        g_pen[b]    = valid ? fmaxf(maxhm - yp, 0.0f) : 0.0f;
    }
}

__global__ __launch_bounds__(256)
void vil_finalize_kernel(float* __restrict__ out, int out_size)
{
    __shared__ float sm1[256];
    __shared__ float sm2[256];
    const int tid = threadIdx.x;
    float s1 = 0.0f, s2 = 0.0f;
    for (int i = tid; i < NB; i += 256) {   // fixed order -> deterministic
        s1 += g_logmse[i];
        s2 += g_pen[i];
    }
    sm1[tid] = s1;
    sm2[tid] = s2;
    __syncthreads();
#pragma unroll
    for (int stride = 128; stride; stride >>= 1) {
        if (tid < stride) {
            sm1[tid] += sm1[tid + stride];
            sm2[tid] += sm2[tid + stride];
        }
        __syncthreads();
    }
    if (tid == 0) {
        float logmse = sm1[0] / (float)NB;
        float viol   = sm2[0] / (float)NB;
        float total  = logmse + LAMB * viol;
        out[0] = total;
        if (out_size > 1) out[1] = logmse;
        if (out_size > 2) out[2] = viol;
    }
}

extern "C" void kernel_launch(void* const* d_in, const int* in_sizes, int n_in,
                              void* d_out, int out_size)
{
    const float* y_pred = (const float*)d_in[0];
    const float* y_true = (const float*)d_in[1];
    const float* Pmat   = (const float*)d_in[2];
    const float* params = (const float*)d_in[3];
    const float* Xs     = (const float*)d_in[4];

    vil_main_kernel<<<NB, 256>>>(y_pred, y_true, Pmat, params, Xs);
    vil_finalize_kernel<<<1, 256>>>((float*)d_out, out_size);
}

// round 3
// speedup vs baseline: 1.3120x; 1.3120x over previous
#include <cuda_runtime.h>

#define NB    2048
#define KD    256
#define PD    256
#define SD    10
#define PADS  12          // xst row stride in floats (10 used + 2 pad, 48B rows, 16B aligned)
#define LAMB  0.5f
#define EPSF  1e-9f
#define NEG_PAD -1e30f

__device__ float g_logmse[NB];
__device__ float g_pen[NB];

typedef unsigned long long ull;

__device__ __forceinline__ ull ffma2(ull a, ull b, ull c) {
    ull d;
    asm("fma.rn.f32x2 %0, %1, %2, %3;" : "=l"(d) : "l"(a), "l"(b), "l"(c));
    return d;
}
__device__ __forceinline__ ull pack2(float x) {
    unsigned u = __float_as_uint(x);
    ull d;
    asm("mov.b64 %0, {%1, %2};" : "=l"(d) : "r"(u), "r"(u));
    return d;
}
__device__ __forceinline__ void unpack2(ull a, float& lo, float& hi) {
    unsigned l, h;
    asm("mov.b64 {%0, %1}, %2;" : "=r"(l), "=r"(h) : "l"(a));
    lo = __uint_as_float(l);
    hi = __uint_as_float(h);
}

__global__ __launch_bounds__(256, 3)
void vil_main_kernel(const float* __restrict__ y_pred,
                     const float* __restrict__ y_true,
                     const float* __restrict__ Pmat,
                     const float* __restrict__ params,
                     const float* __restrict__ Xs)
{
    __shared__ float xst[KD * PADS];   // X transposed+masked: xst[kk*PADS + s]  (12 KB)
    __shared__ float cp[SD * PD];      // masked |X@P|                            (10 KB)
    __shared__ float warr[8];          // per-warp max h_m

    const int b    = blockIdx.x;
    const int tid  = threadIdx.x;
    const int lane = tid & 31;
    const int warp = tid >> 5;

    int n = (int)params[b * 3 + 0];
    int k = (int)params[b * 3 + 1];
    int m = (int)params[b * 3 + 2];
    if (k > KD) k = KD;
    int pv = n - k;
    if (pv < 0) pv = 0;
    if (pv > PD) pv = PD;
    if (m < 0) m = 0;
    if (m > 8) m = 8;

    // ---- stage X transposed + masked into smem ----
    const float* Xb = Xs + (size_t)b * SD * KD;
    for (int i = tid; i < SD * KD; i += 256) {
        int s  = i >> 8;          // KD = 256
        int kk = i & (KD - 1);
        float v = Xb[i];
        xst[kk * PADS + s] = (kk < k) ? v : 0.0f;
    }
    __syncthreads();

    // ---- GEMM: 5 packed f32x2 accumulators (s-pairs), one output column per thread ----
    const float* Pb = Pmat + (size_t)b * KD * PD + tid;
    ull a0 = 0ull, a1 = 0ull, a2 = 0ull, a3 = 0ull, a4 = 0ull;

    float pr[8];
#pragma unroll
    for (int u = 0; u < 8; ++u) pr[u] = Pb[u * PD];

    for (int kk0 = 0; kk0 < KD; kk0 += 8) {
        float pc[8];
#pragma unroll
        for (int u = 0; u < 8; ++u) pc[u] = pr[u];
        if (kk0 + 8 < KD) {
#pragma unroll
            for (int u = 0; u < 8; ++u) pr[u] = Pb[(kk0 + 8 + u) * PD];
        }
#pragma unroll
        for (int u = 0; u < 8; ++u) {
            const float* row = xst + (kk0 + u) * PADS;
            ulonglong2 q0 = *reinterpret_cast<const ulonglong2*>(row);      // s0..s3
            ulonglong2 q1 = *reinterpret_cast<const ulonglong2*>(row + 4);  // s4..s7
            ull x89       = *reinterpret_cast<const ull*>(row + 8);         // s8,s9
            ull pp = pack2(pc[u]);
            a0 = ffma2(q0.x, pp, a0);
            a1 = ffma2(q0.y, pp, a1);
            a2 = ffma2(q1.x, pp, a2);
            a3 = ffma2(q1.y, pp, a3);
            a4 = ffma2(x89,  pp, a4);
        }
    }

    // ---- write masked |C_p| to smem ----
    {
        float c[SD];
        unpack2(a0, c[0], c[1]);
        unpack2(a1, c[2], c[3]);
        unpack2(a2, c[4], c[5]);
        unpack2(a3, c[6], c[7]);
        unpack2(a4, c[8], c[9]);
        bool okp = tid < pv;
#pragma unroll
        for (int s = 0; s < SD; ++s)
            cp[s * PD + tid] = okp ? fabsf(c[s]) : -1.0f;
    }
    __syncthreads();

    // ---- selection: one warp per s (warps 0,1 take a second s) ----
    float s_hm = 0.0f;
    for (int s = warp; s < SD; s += 8) {
        float t[9];
#pragma unroll
        for (int i = 0; i < 9; ++i) t[i] = NEG_PAD;

        // 16 candidates per lane: 8 from X part, 8 from X@P part
#pragma unroll
        for (int j = 0; j < 8; ++j) {
            int kk = lane + 32 * j;
            float v = (kk < k) ? fabsf(xst[kk * PADS + s]) : -1.0f;
#pragma unroll
            for (int i = 8; i >= 1; --i) t[i] = fmaxf(t[i], fminf(t[i - 1], v));
            t[0] = fmaxf(t[0], v);
        }
#pragma unroll
        for (int j = 0; j < 8; ++j) {
            float v = cp[s * PD + lane + 32 * j];
#pragma unroll
            for (int i = 8; i >= 1; --i) t[i] = fmaxf(t[i], fminf(t[i - 1], v));
            t[0] = fmaxf(t[0], v);
        }

        // butterfly merge of sorted top-9 lists across 32 lanes
#pragma unroll
        for (int st = 0; st < 5; ++st) {
            float r[9], o[9];
#pragma unroll
            for (int i = 0; i < 9; ++i)
                r[i] = __shfl_xor_sync(0xffffffffu, t[i], 1 << st);
#pragma unroll
            for (int j = 0; j < 9; ++j) {
                float mx = fmaxf(t[j], r[j]);
#pragma unroll
                for (int i = 0; i < j; ++i)
                    mx = fmaxf(mx, fminf(t[i], r[j - 1 - i]));
                o[j] = mx;
            }
#pragma unroll
            for (int i = 0; i < 9; ++i) t[i] = o[i];
        }

        float topm = t[0];
#pragma unroll
        for (int i = 1; i < 9; ++i)
            if (m == i) topm = t[i];

        s_hm = fmaxf(s_hm, t[0] / (topm + EPSF));
    }
    if (lane == 0) warr[warp] = s_hm;
    __syncthreads();

    // ---- per-batch scalar outputs ----
    if (tid == 0) {
        float mh = warr[0];
#pragma unroll
        for (int w = 1; w < 8; ++w) mh = fmaxf(mh, warr[w]);
        float yp = y_pred[b];
        float lt = log2f(fmaxf(y_true[b], EPSF));
        float lp = log2f(fmaxf(yp, EPSF));
        float d  = lt - lp;
        g_logmse[b] = d * d;
        bool valid  = (m + 1) <= n;
        g_pen[b]    = valid ? fmaxf(mh - yp, 0.0f) : 0.0f;
    }
}

__global__ __launch_bounds__(256)
void vil_finalize_kernel(float* __restrict__ out, int out_size)
{
    __shared__ float sm1[256];
    __shared__ float sm2[256];
    const int tid = threadIdx.x;
    float s1 = 0.0f, s2 = 0.0f;
    for (int i = tid; i < NB; i += 256) {   // fixed order -> deterministic
        s1 += g_logmse[i];
        s2 += g_pen[i];
    }
    sm1[tid] = s1;
    sm2[tid] = s2;
    __syncthreads();
#pragma unroll
    for (int stride = 128; stride; stride >>= 1) {
        if (tid < stride) {
            sm1[tid] += sm1[tid + stride];
            sm2[tid] += sm2[tid + stride];
        }
        __syncthreads();
    }
    if (tid == 0) {
        float logmse = sm1[0] / (float)NB;
        float viol   = sm2[0] / (float)NB;
        float total  = logmse + LAMB * viol;
        out[0] = total;
        if (out_size > 1) out[1] = logmse;
        if (out_size > 2) out[2] = viol;
    }
}

// empty filler so the ncu capture (-s 5 -c 1, 5-launch period) lands on vil_main_kernel
__global__ void vil_nop_kernel() {}

extern "C" void kernel_launch(void* const* d_in, const int* in_sizes, int n_in,
                              void* d_out, int out_size)
{
    const float* y_pred = (const float*)d_in[0];
    const float* y_true = (const float*)d_in[1];
    const float* Pmat   = (const float*)d_in[2];
    const float* params = (const float*)d_in[3];
    const float* Xs     = (const float*)d_in[4];

    vil_main_kernel<<<NB, 256>>>(y_pred, y_true, Pmat, params, Xs);
    vil_finalize_kernel<<<1, 256>>>((float*)d_out, out_size);
    vil_nop_kernel<<<1, 32>>>();
    vil_nop_kernel<<<1, 32>>>();
    vil_nop_kernel<<<1, 32>>>();
}

// round 4
// speedup vs baseline: 1.5607x; 1.1895x over previous
#include <cuda_runtime.h>

#define NB    2048
#define KD    256
#define PD    256
#define SD    10
#define PADS  12          // xst row stride in floats (10 used + 2 pad)
#define LAMB  0.5f
#define EPSF  1e-9f
#define NEG_PAD -1e30f
#define PF    16          // prefetch depth (rows of P in flight per thread)

__device__ float    g_logmse[NB];
__device__ float    g_pen[NB];
__device__ unsigned g_done = 0;

typedef unsigned long long ull;

__device__ __forceinline__ ull ffma2(ull a, ull b, ull c) {
    ull d;
    asm("fma.rn.f32x2 %0, %1, %2, %3;" : "=l"(d) : "l"(a), "l"(b), "l"(c));
    return d;
}
__device__ __forceinline__ ull pack2(float x) {
    unsigned u = __float_as_uint(x);
    ull d;
    asm("mov.b64 %0, {%1, %2};" : "=l"(d) : "r"(u), "r"(u));
    return d;
}
__device__ __forceinline__ void unpack2(ull a, float& lo, float& hi) {
    unsigned l, h;
    asm("mov.b64 {%0, %1}, %2;" : "=r"(l), "=r"(h) : "l"(a));
    lo = __uint_as_float(l);
    hi = __uint_as_float(h);
}

__global__ __launch_bounds__(256, 3)
void vil_main_kernel(const float* __restrict__ y_pred,
                     const float* __restrict__ y_true,
                     const float* __restrict__ Pmat,
                     const float* __restrict__ params,
                     const float* __restrict__ Xs,
                     float* __restrict__ out,
                     int out_size)
{
    __shared__ float xst[KD * PADS];   // X transposed+masked: xst[kk*PADS + s]
    __shared__ float cp[SD * PD];      // masked |X@P|
    __shared__ float warr[8];          // per-warp max h_m
    __shared__ unsigned is_last;

    const int b    = blockIdx.x;
    const int tid  = threadIdx.x;
    const int lane = tid & 31;
    const int warp = tid >> 5;

    int n = (int)params[b * 3 + 0];
    int k = (int)params[b * 3 + 1];
    int m = (int)params[b * 3 + 2];
    if (k > KD) k = KD;
    int pv = n - k;
    if (pv < 0) pv = 0;
    if (pv > PD) pv = PD;
    if (m < 0) m = 0;
    if (m > 8) m = 8;

    // ---- stage X transposed + masked into smem ----
    const float* Xb = Xs + (size_t)b * SD * KD;
    for (int i = tid; i < SD * KD; i += 256) {
        int s  = i >> 8;          // KD = 256
        int kk = i & (KD - 1);
        float v = Xb[i];
        xst[kk * PADS + s] = (kk < k) ? v : 0.0f;
    }
    __syncthreads();

    // ---- GEMM: 5 packed f32x2 accumulators, one output column per thread ----
    const float* Pb = Pmat + (size_t)b * KD * PD + tid;
    ull a0 = 0ull, a1 = 0ull, a2 = 0ull, a3 = 0ull, a4 = 0ull;

    float pr[PF];
#pragma unroll
    for (int u = 0; u < PF; ++u) pr[u] = Pb[u * PD];

    for (int kk0 = 0; kk0 < KD; kk0 += PF) {
        float pc[PF];
#pragma unroll
        for (int u = 0; u < PF; ++u) pc[u] = pr[u];
        if (kk0 + PF < KD) {
#pragma unroll
            for (int u = 0; u < PF; ++u) pr[u] = Pb[(kk0 + PF + u) * PD];
        }
#pragma unroll
        for (int u = 0; u < PF; ++u) {
            const float* row = xst + (kk0 + u) * PADS;
            ulonglong2 q0 = *reinterpret_cast<const ulonglong2*>(row);      // s0..s3
            ulonglong2 q1 = *reinterpret_cast<const ulonglong2*>(row + 4);  // s4..s7
            ull x89       = *reinterpret_cast<const ull*>(row + 8);         // s8,s9
            ull pp = pack2(pc[u]);
            a0 = ffma2(q0.x, pp, a0);
            a1 = ffma2(q0.y, pp, a1);
            a2 = ffma2(q1.x, pp, a2);
            a3 = ffma2(q1.y, pp, a3);
            a4 = ffma2(x89,  pp, a4);
        }
    }

    // ---- write masked |C_p| to smem ----
    {
        float c[SD];
        unpack2(a0, c[0], c[1]);
        unpack2(a1, c[2], c[3]);
        unpack2(a2, c[4], c[5]);
        unpack2(a3, c[6], c[7]);
        unpack2(a4, c[8], c[9]);
        bool okp = tid < pv;
#pragma unroll
        for (int s = 0; s < SD; ++s)
            cp[s * PD + tid] = okp ? fabsf(c[s]) : -1.0f;
    }
    __syncthreads();

    // ---- selection: one warp per s (warps 0,1 take a second s) ----
    float s_hm = 0.0f;
    for (int s = warp; s < SD; s += 8) {
        float t[9];
#pragma unroll
        for (int i = 0; i < 9; ++i) t[i] = NEG_PAD;

        // 16 candidates per lane: 8 from X part, 8 from X@P part
#pragma unroll
        for (int j = 0; j < 8; ++j) {
            int kk = lane + 32 * j;
            float v = (kk < k) ? fabsf(xst[kk * PADS + s]) : -1.0f;
#pragma unroll
            for (int i = 8; i >= 1; --i) t[i] = fmaxf(t[i], fminf(t[i - 1], v));
            t[0] = fmaxf(t[0], v);
        }
#pragma unroll
        for (int j = 0; j < 8; ++j) {
            float v = cp[s * PD + lane + 32 * j];
#pragma unroll
            for (int i = 8; i >= 1; --i) t[i] = fmaxf(t[i], fminf(t[i - 1], v));
            t[0] = fmaxf(t[0], v);
        }

        // butterfly merge of sorted top-9 lists across 32 lanes
#pragma unroll
        for (int st = 0; st < 5; ++st) {
            float r[9], o[9];
#pragma unroll
            for (int i = 0; i < 9; ++i)
                r[i] = __shfl_xor_sync(0xffffffffu, t[i], 1 << st);
#pragma unroll
            for (int j = 0; j < 9; ++j) {
                float mx = fmaxf(t[j], r[j]);
#pragma unroll
                for (int i = 0; i < j; ++i)
                    mx = fmaxf(mx, fminf(t[i], r[j - 1 - i]));
                o[j] = mx;
            }
#pragma unroll
            for (int i = 0; i < 9; ++i) t[i] = o[i];
        }

        float topm = t[0];
#pragma unroll
        for (int i = 1; i < 9; ++i)
            if (m == i) topm = t[i];

        s_hm = fmaxf(s_hm, t[0] / (topm + EPSF));
    }
    if (lane == 0) warr[warp] = s_hm;
    __syncthreads();

    // ---- per-batch scalar outputs ----
    if (tid == 0) {
        float mh = warr[0];
#pragma unroll
        for (int w = 1; w < 8; ++w) mh = fmaxf(mh, warr[w]);
        float yp = y_pred[b];
        float lt = log2f(fmaxf(y_true[b], EPSF));
        float lp = log2f(fmaxf(yp, EPSF));
        float d  = lt - lp;
        g_logmse[b] = d * d;
        bool valid  = (m + 1) <= n;
        g_pen[b]    = valid ? fmaxf(mh - yp, 0.0f) : 0.0f;
        __threadfence();
        unsigned prev = atomicAdd(&g_done, 1u);
        is_last = (prev == NB - 1) ? 1u : 0u;
    } 
    __syncthreads();

    // ---- last block performs the deterministic final reduction ----
    if (is_last) {
        __threadfence();   // acquire: make all blocks' g_ writes visible
        __shared__ float sm1[256];
        __shared__ float sm2[256];
        float s1 = 0.0f, s2 = 0.0f;
        for (int i = tid; i < NB; i += 256) {   // fixed order -> deterministic
            s1 += g_logmse[i];
            s2 += g_pen[i];
        }
        sm1[tid] = s1;
        sm2[tid] = s2;
        __syncthreads();
#pragma unroll
        for (int stride = 128; stride; stride >>= 1) {
            if (tid < stride) {
                sm1[tid] += sm1[tid + stride];
                sm2[tid] += sm2[tid + stride];
            }
            __syncthreads();
        }
        if (tid == 0) {
            float logmse = sm1[0] / (float)NB;
            float viol   = sm2[0] / (float)NB;
            float total  = logmse + LAMB * viol;
            out[0] = total;
            if (out_size > 1) out[1] = logmse;
            if (out_size > 2) out[2] = viol;
            g_done = 0;   // reset for next graph replay
        }
    }
}

extern "C" void kernel_launch(void* const* d_in, const int* in_sizes, int n_in,
                              void* d_out, int out_size)
{
    const float* y_pred = (const float*)d_in[0];
    const float* y_true = (const float*)d_in[1];
    const float* Pmat   = (const float*)d_in[2];
    const float* params = (const float*)d_in[3];
    const float* Xs     = (const float*)d_in[4];

    vil_main_kernel<<<NB, 256>>>(y_pred, y_true, Pmat, params, Xs,
                                 (float*)d_out, out_size);
}